// round 3
// baseline (speedup 1.0000x reference)
#include <cuda_runtime.h>
#include <math.h>

// Problem constants
#define DD 256
#define KK 4096
#define LLEN 4096
#define BB 8
#define NN (BB * LLEN)          // 32768 tokens
#define VV (BB * DD * LLEN)     // 8388608 output elements

// GEMM tiling
#define BM 128
#define BN 128
#define BDK 16
#define SP 132                  // smem pitch (128 + 4 pad, keeps 16B alignment)

// ---- scratch (device globals: allocation-free per harness rules) ----
__device__ float g_what[KK * DD];       // 4 MB normalized codes
__device__ float g_xT[NN * DD];         // 32 MB token-major inputs
__device__ int   g_idx[NN];
__device__ int   g_hist[KK];
__device__ float g_partials[8192];

// packed f32x2 FMA: d = a*b + d (two fp32 lanes per instruction -> full 128 FMA/SM/cyc)
__device__ __forceinline__ void fma2(unsigned long long& d, unsigned long long a,
                                     unsigned long long b) {
    asm("fma.rn.f32x2 %0, %1, %2, %0;" : "+l"(d) : "l"(a), "l"(b));
}
__device__ __forceinline__ unsigned long long dup2(float a) {
    unsigned long long r;
    asm("mov.b64 %0, {%1, %1};" : "=l"(r) : "r"(__float_as_uint(a)));
    return r;
}

// ---------------- kernel A: normalize weight rows ----------------
// one warp per code row; grid 512 x 256 threads
__global__ void k_norm_w(const float* __restrict__ w) {
    int row  = blockIdx.x * 8 + (threadIdx.x >> 5);
    int lane = threadIdx.x & 31;
    const float4* src = (const float4*)(w + (size_t)row * DD);
    float4 a = src[lane];
    float4 b = src[lane + 32];
    float s = a.x*a.x + a.y*a.y + a.z*a.z + a.w*a.w
            + b.x*b.x + b.y*b.y + b.z*b.z + b.w*b.w;
#pragma unroll
    for (int o = 16; o; o >>= 1) s += __shfl_xor_sync(0xffffffffu, s, o);
    float inv = 1.0f / fmaxf(sqrtf(s), 1e-12f);
    float4* dst = (float4*)(g_what + (size_t)row * DD);
    a.x *= inv; a.y *= inv; a.z *= inv; a.w *= inv;
    b.x *= inv; b.y *= inv; b.z *= inv; b.w *= inv;
    dst[lane] = a;
    dst[lane + 32] = b;
}

// ---------------- kernel B: transpose inputs [B,D,L] -> xT [B*L, D] ----------------
__global__ void k_transpose(const float* __restrict__ in) {
    __shared__ float tile[32][33];
    int b  = blockIdx.z;
    int d0 = blockIdx.y * 32;
    int l0 = blockIdx.x * 32;
    int tx = threadIdx.x, ty = threadIdx.y;   // 32 x 8
    const float* src = in + ((size_t)b * DD + d0) * (size_t)LLEN + l0;
#pragma unroll
    for (int r = 0; r < 32; r += 8)
        tile[ty + r][tx] = src[(size_t)(ty + r) * LLEN + tx];
    __syncthreads();
    float* dst = g_xT + ((size_t)b * LLEN + l0) * DD + d0;
#pragma unroll
    for (int r = 0; r < 32; r += 8)
        dst[(size_t)(ty + r) * DD + tx] = tile[tx][ty + r];
}

// ---------------- kernel C: fused fp32 GEMM + argmax ----------------
// grid 256 blocks (128 tokens each), 256 threads (16x16), FFMA2 inner loop.
__global__ __launch_bounds__(256, 2) void k_argmax() {
    __shared__ float sA[2][BDK][SP];
    __shared__ float sB[2][BDK][SP];

    int tid = threadIdx.x;
    int tx = tid & 15, ty = tid >> 4;
    int m0 = blockIdx.x * BM;

    float bestv[8];
    int   bestc[8];
#pragma unroll
    for (int i = 0; i < 8; i++) { bestv[i] = -3.4e38f; bestc[i] = 0x7fffffff; }

    // loader mapping: each thread streams 2 float4 of A and 2 of B per 16-dim slab
    int la_tok  = tid >> 2;      // 0..63
    int la_dseg = tid & 3;       // 0..3 -> dims dseg*4..+3 within the slab
    const float* Abase = g_xT + (size_t)m0 * DD;

    for (int kt = 0; kt < KK; kt += BN) {
        const float* Bbase = g_what + (size_t)kt * DD;

        unsigned long long acc[8][4];
#pragma unroll
        for (int i = 0; i < 8; i++)
#pragma unroll
            for (int j = 0; j < 4; j++) acc[i][j] = 0ull;

        // prologue: load slab 0
        int doff = la_dseg * 4;
        float4 ra0 = *(const float4*)(Abase + (size_t)la_tok * DD + doff);
        float4 ra1 = *(const float4*)(Abase + (size_t)(la_tok + 64) * DD + doff);
        float4 rb0 = *(const float4*)(Bbase + (size_t)la_tok * DD + doff);
        float4 rb1 = *(const float4*)(Bbase + (size_t)(la_tok + 64) * DD + doff);
        {
            int tr = la_dseg * 4;
            sA[0][tr+0][la_tok] = ra0.x; sA[0][tr+1][la_tok] = ra0.y;
            sA[0][tr+2][la_tok] = ra0.z; sA[0][tr+3][la_tok] = ra0.w;
            sA[0][tr+0][la_tok+64] = ra1.x; sA[0][tr+1][la_tok+64] = ra1.y;
            sA[0][tr+2][la_tok+64] = ra1.z; sA[0][tr+3][la_tok+64] = ra1.w;
            sB[0][tr+0][la_tok] = rb0.x; sB[0][tr+1][la_tok] = rb0.y;
            sB[0][tr+2][la_tok] = rb0.z; sB[0][tr+3][la_tok] = rb0.w;
            sB[0][tr+0][la_tok+64] = rb1.x; sB[0][tr+1][la_tok+64] = rb1.y;
            sB[0][tr+2][la_tok+64] = rb1.z; sB[0][tr+3][la_tok+64] = rb1.w;
        }
        __syncthreads();

#pragma unroll 1
        for (int dtb = 0; dtb < DD / BDK; ++dtb) {
            int cur = dtb & 1;
            if (dtb < DD / BDK - 1) {
                int od = (dtb + 1) * BDK + la_dseg * 4;
                ra0 = *(const float4*)(Abase + (size_t)la_tok * DD + od);
                ra1 = *(const float4*)(Abase + (size_t)(la_tok + 64) * DD + od);
                rb0 = *(const float4*)(Bbase + (size_t)la_tok * DD + od);
                rb1 = *(const float4*)(Bbase + (size_t)(la_tok + 64) * DD + od);
            }
#pragma unroll
            for (int d = 0; d < BDK; ++d) {
                float4 a0 = *(const float4*)&sA[cur][d][ty * 4];
                float4 a1 = *(const float4*)&sA[cur][d][64 + ty * 4];
                ulonglong2 b0 = *(const ulonglong2*)&sB[cur][d][tx * 4];
                ulonglong2 b1 = *(const ulonglong2*)&sB[cur][d][64 + tx * 4];
                float av[8] = {a0.x, a0.y, a0.z, a0.w, a1.x, a1.y, a1.z, a1.w};
#pragma unroll
                for (int i = 0; i < 8; i++) {
                    unsigned long long ap = dup2(av[i]);
                    fma2(acc[i][0], ap, b0.x);
                    fma2(acc[i][1], ap, b0.y);
                    fma2(acc[i][2], ap, b1.x);
                    fma2(acc[i][3], ap, b1.y);
                }
            }
            if (dtb < DD / BDK - 1) {
                int nb = cur ^ 1;
                int tr = la_dseg * 4;
                sA[nb][tr+0][la_tok] = ra0.x; sA[nb][tr+1][la_tok] = ra0.y;
                sA[nb][tr+2][la_tok] = ra0.z; sA[nb][tr+3][la_tok] = ra0.w;
                sA[nb][tr+0][la_tok+64] = ra1.x; sA[nb][tr+1][la_tok+64] = ra1.y;
                sA[nb][tr+2][la_tok+64] = ra1.z; sA[nb][tr+3][la_tok+64] = ra1.w;
                sB[nb][tr+0][la_tok] = rb0.x; sB[nb][tr+1][la_tok] = rb0.y;
                sB[nb][tr+2][la_tok] = rb0.z; sB[nb][tr+3][la_tok] = rb0.w;
                sB[nb][tr+0][la_tok+64] = rb1.x; sB[nb][tr+1][la_tok+64] = rb1.y;
                sB[nb][tr+2][la_tok+64] = rb1.z; sB[nb][tr+3][la_tok+64] = rb1.w;
            }
            __syncthreads();
        }

        // epilogue: per-token max over this tile's 128 codes, then running best
#pragma unroll
        for (int i = 0; i < 8; i++) {
            float v = -3.4e38f;
            int   c = 0x7fffffff;
#pragma unroll
            for (int jp = 0; jp < 4; jp++) {  // ascending code order -> first-max ties
                float lo = __int_as_float((int)(acc[i][jp] & 0xffffffffull));
                float hi = __int_as_float((int)(acc[i][jp] >> 32));
                int cl = kt + ((jp >> 1) << 6) + tx * 4 + ((jp & 1) << 1);
                if (lo > v) { v = lo; c = cl; }
                if (hi > v) { v = hi; c = cl + 1; }
            }
#pragma unroll
            for (int o = 8; o; o >>= 1) {  // 16-lane butterfly (stays in half-warp)
                float ov = __shfl_xor_sync(0xffffffffu, v, o);
                int   oc = __shfl_xor_sync(0xffffffffu, c, o);
                if (ov > v || (ov == v && oc < c)) { v = ov; c = oc; }
            }
            if (v > bestv[i] || (v == bestv[i] && c < bestc[i])) {
                bestv[i] = v; bestc[i] = c;
            }
        }
    }

    if (tx == 0) {
#pragma unroll
        for (int i = 0; i < 8; i++) {
            int m = m0 + ty * 4 + (i & 3) + ((i >> 2) << 6);
            g_idx[m] = bestc[i];
        }
    }
}

// ---------------- kernel D: gather codes -> output + loss partials ----------------
__global__ void k_gather(const float* __restrict__ in, const float* __restrict__ w,
                         float* __restrict__ out) {
    __shared__ float red[256];
    int g = blockIdx.x * 256 + threadIdx.x;   // 0 .. VV/4-1
    int m = g << 2;                           // element index in [B,D,L] linear
    int b   = m >> 20;                        // / (D*L)
    int rem = m & ((1 << 20) - 1);
    int d   = rem >> 12;                      // / L
    int l   = rem & (LLEN - 1);
    int n   = (b << 12) + l;
    int4 id4 = *(const int4*)(g_idx + n);
    float4 xv = *(const float4*)(in + m);
    float4 q;
    q.x = w[(size_t)id4.x * DD + d];
    q.y = w[(size_t)id4.y * DD + d];
    q.z = w[(size_t)id4.z * DD + d];
    q.w = w[(size_t)id4.w * DD + d];
    *(float4*)(out + m) = q;
    float dx = q.x - xv.x, dy = q.y - xv.y, dz = q.z - xv.z, dw = q.w - xv.w;
    red[threadIdx.x] = dx*dx + dy*dy + dz*dz + dw*dw;
    __syncthreads();
#pragma unroll
    for (int o = 128; o; o >>= 1) {
        if (threadIdx.x < o) red[threadIdx.x] += red[threadIdx.x + o];
        __syncthreads();
    }
    if (threadIdx.x == 0) g_partials[blockIdx.x] = red[0];
}

// ---------------- histogram ----------------
__global__ void k_zero_hist() { g_hist[blockIdx.x * 256 + threadIdx.x] = 0; }   // grid 16
__global__ void k_hist() {                                                      // grid 128
    int g = blockIdx.x * 256 + threadIdx.x;
    atomicAdd(&g_hist[g_idx[g]], 1);
}

// ---------------- final scalars: loss + perplexity ----------------
__global__ void k_final(float* __restrict__ out, int out_size) {
    __shared__ float red[256];
    int t = threadIdx.x;
    float s = 0.0f;
    for (int k = t; k < 8192; k += 256) s += g_partials[k];
    red[t] = s; __syncthreads();
#pragma unroll
    for (int o = 128; o; o >>= 1) { if (t < o) red[t] += red[t + o]; __syncthreads(); }
    float loss = 1.25f * red[0] / (float)VV;
    __syncthreads();
    float p = 0.0f;
    for (int k = t; k < KK; k += 256) {
        float pv = (float)g_hist[k] * (1.0f / (float)NN);
        p += pv * logf(pv + 1e-10f);
    }
    red[t] = p; __syncthreads();
#pragma unroll
    for (int o = 128; o; o >>= 1) { if (t < o) red[t] += red[t + o]; __syncthreads(); }
    if (t == 0 && out_size >= VV + 2) {
        out[VV]     = loss;
        out[VV + 1] = expf(-red[0]);
    }
}

extern "C" void kernel_launch(void* const* d_in, const int* in_sizes, int n_in,
                              void* d_out, int out_size) {
    const float* inputs = (const float*)d_in[0];
    const float* weight = (const float*)d_in[1];
    if (n_in >= 2 && in_sizes[0] == KK * DD && in_sizes[1] == VV) {
        inputs = (const float*)d_in[1];
        weight = (const float*)d_in[0];
    }
    float* out = (float*)d_out;

    k_norm_w<<<512, 256>>>(weight);
    k_transpose<<<dim3(LLEN / 32, DD / 32, BB), dim3(32, 8)>>>(inputs);
    k_argmax<<<NN / BM, 256>>>();
    k_gather<<<VV / 1024, 256>>>(inputs, weight, out);
    k_zero_hist<<<KK / 256, 256>>>();
    k_hist<<<NN / 256, 256>>>();
    k_final<<<1, 256>>>(out, out_size);
}

// round 4
// speedup vs baseline: 1.6692x; 1.6692x over previous
#include <cuda_runtime.h>
#include <cuda_fp16.h>
#include <cuda_bf16.h>
#include <math.h>

// Problem constants
#define DD 256
#define KK 4096
#define LLEN 4096
#define BB 8
#define NN (BB * LLEN)          // 32768 tokens
#define VV (BB * DD * LLEN)     // 8388608 output elements

#define APITCH 264              // smem pitch for A tile (bf16 elems): conflict-free + 16B rows
#define BPITCH 72               // smem pitch for B slab (64 dims + 8 pad)
#define MARGIN 0.03f            // candidate threshold (>> 2*max approx error)

// ---- scratch (device globals: allocation-free per harness rules) ----
__device__ float          g_what[KK * DD];   // 4 MB normalized codes fp32
__device__ __nv_bfloat16  g_whath[KK * DD];  // 2 MB normalized codes bf16
__device__ float          g_xT[NN * DD];     // 32 MB token-major inputs fp32
__device__ __nv_bfloat16  g_xTh[NN * DD];    // 16 MB token-major inputs bf16
__device__ __half         g_sim[(size_t)NN * KK]; // 256 MB approx sims
__device__ int            g_idx[NN];
__device__ int            g_hist[KK];
__device__ float          g_partials[8192];

// ---------------- kernel A: normalize weight rows (fp32 + bf16) ----------------
__global__ void k_norm_w(const float* __restrict__ w) {
    int row  = blockIdx.x * 8 + (threadIdx.x >> 5);
    int lane = threadIdx.x & 31;
    const float4* src = (const float4*)(w + (size_t)row * DD);
    float4 a = src[lane];
    float4 b = src[lane + 32];
    float s = a.x*a.x + a.y*a.y + a.z*a.z + a.w*a.w
            + b.x*b.x + b.y*b.y + b.z*b.z + b.w*b.w;
#pragma unroll
    for (int o = 16; o; o >>= 1) s += __shfl_xor_sync(0xffffffffu, s, o);
    float inv = 1.0f / fmaxf(sqrtf(s), 1e-12f);
    a.x *= inv; a.y *= inv; a.z *= inv; a.w *= inv;
    b.x *= inv; b.y *= inv; b.z *= inv; b.w *= inv;
    float4* dst = (float4*)(g_what + (size_t)row * DD);
    dst[lane] = a;
    dst[lane + 32] = b;
    __nv_bfloat16* dh = g_whath + (size_t)row * DD;
    int c0 = lane * 4, c1 = (lane + 32) * 4;
    dh[c0+0] = __float2bfloat16(a.x); dh[c0+1] = __float2bfloat16(a.y);
    dh[c0+2] = __float2bfloat16(a.z); dh[c0+3] = __float2bfloat16(a.w);
    dh[c1+0] = __float2bfloat16(b.x); dh[c1+1] = __float2bfloat16(b.y);
    dh[c1+2] = __float2bfloat16(b.z); dh[c1+3] = __float2bfloat16(b.w);
}

// ---------------- kernel B: transpose [B,D,L] -> xT [N,D] (fp32 + bf16) ----------------
__global__ void k_transpose(const float* __restrict__ in) {
    __shared__ float tile[32][33];
    int b  = blockIdx.z;
    int d0 = blockIdx.y * 32;
    int l0 = blockIdx.x * 32;
    int tx = threadIdx.x, ty = threadIdx.y;   // 32 x 8
    const float* src = in + ((size_t)b * DD + d0) * (size_t)LLEN + l0;
#pragma unroll
    for (int r = 0; r < 32; r += 8)
        tile[ty + r][tx] = src[(size_t)(ty + r) * LLEN + tx];
    __syncthreads();
    size_t base = ((size_t)b * LLEN + l0) * DD + d0;
    float* dst = g_xT + base;
    __nv_bfloat16* dsth = g_xTh + base;
#pragma unroll
    for (int r = 0; r < 32; r += 8) {
        float v = tile[tx][ty + r];
        dst[(size_t)(ty + r) * DD + tx]  = v;
        dsth[(size_t)(ty + r) * DD + tx] = __float2bfloat16(v);
    }
}

// ---------------- kernel C: bf16 MMA sim matrix [N,K] fp16 ----------------
// 256 blocks x 256 threads. Block = 128 tokens, loops all 4096 codes.
// 8 warps as 4(M) x 2(N): warp tile 32 tokens x 64 codes.
__global__ __launch_bounds__(256, 2) void k_sim() {
    extern __shared__ __nv_bfloat16 smem[];
    __nv_bfloat16* sA = smem;                       // [128][APITCH]
    __nv_bfloat16* sB = smem + 128 * APITCH;        // [2][128][BPITCH]

    int tid  = threadIdx.x;
    int warp = tid >> 5, lane = tid & 31;
    int wm = warp >> 1, wn = warp & 1;
    int g = lane >> 2, q = lane & 3;
    int m0 = blockIdx.x * 128;

    // Load full A tile: 128 tokens x 256 dims bf16
#pragma unroll
    for (int i = 0; i < 16; i++) {
        int cid = tid + i * 256;
        int row = cid >> 5, ch = cid & 31;
        *(uint4*)&sA[row * APITCH + ch * 8] =
            *(const uint4*)&g_xTh[(size_t)(m0 + row) * DD + ch * 8];
    }
    // Load B slab 0 of kt=0 (dims 0..63 of codes 0..127)
#pragma unroll
    for (int i = 0; i < 4; i++) {
        int cid = tid + i * 256;
        int row = cid >> 3, ch = cid & 7;
        *(uint4*)&sB[row * BPITCH + ch * 8] =
            *(const uint4*)&g_whath[(size_t)row * DD + ch * 8];
    }
    __syncthreads();

    for (int kt = 0; kt < KK; kt += 128) {
        float acc[2][8][4];
#pragma unroll
        for (int mt = 0; mt < 2; mt++)
#pragma unroll
            for (int nt = 0; nt < 8; nt++)
#pragma unroll
                for (int j = 0; j < 4; j++) acc[mt][nt][j] = 0.0f;

#pragma unroll
        for (int s = 0; s < 4; ++s) {
            int cur = s & 1;
            bool hasNext = (s < 3) || (kt + 128 < KK);
            int nkt = (s < 3) ? kt : kt + 128;
            int ns  = (s < 3) ? s + 1 : 0;
            uint4 pre[4];
            if (hasNext) {
#pragma unroll
                for (int i = 0; i < 4; i++) {
                    int cid = tid + i * 256;
                    int row = cid >> 3, ch = cid & 7;
                    pre[i] = *(const uint4*)&g_whath[(size_t)(nkt + row) * DD + ns * 64 + ch * 8];
                }
            }
            const __nv_bfloat16* Bb = sB + cur * (128 * BPITCH);
#pragma unroll
            for (int kk = 0; kk < 4; kk++) {
                int aoff = s * 64 + kk * 16;
                unsigned af[2][4];
#pragma unroll
                for (int mt = 0; mt < 2; mt++) {
                    const __nv_bfloat16* Ap = sA + (wm * 32 + mt * 16 + g) * APITCH + aoff + q * 2;
                    af[mt][0] = *(const unsigned*)(Ap);
                    af[mt][1] = *(const unsigned*)(Ap + 8 * APITCH);
                    af[mt][2] = *(const unsigned*)(Ap + 8);
                    af[mt][3] = *(const unsigned*)(Ap + 8 * APITCH + 8);
                }
                unsigned bf[8][2];
#pragma unroll
                for (int nt = 0; nt < 8; nt++) {
                    const __nv_bfloat16* Bp = Bb + (wn * 64 + nt * 8 + g) * BPITCH + kk * 16 + q * 2;
                    bf[nt][0] = *(const unsigned*)(Bp);
                    bf[nt][1] = *(const unsigned*)(Bp + 8);
                }
#pragma unroll
                for (int mt = 0; mt < 2; mt++)
#pragma unroll
                    for (int nt = 0; nt < 8; nt++) {
                        asm volatile(
                            "mma.sync.aligned.m16n8k16.row.col.f32.bf16.bf16.f32 "
                            "{%0,%1,%2,%3}, {%4,%5,%6,%7}, {%8,%9}, {%0,%1,%2,%3};"
                            : "+f"(acc[mt][nt][0]), "+f"(acc[mt][nt][1]),
                              "+f"(acc[mt][nt][2]), "+f"(acc[mt][nt][3])
                            : "r"(af[mt][0]), "r"(af[mt][1]), "r"(af[mt][2]), "r"(af[mt][3]),
                              "r"(bf[nt][0]), "r"(bf[nt][1]));
                    }
            }
            if (hasNext) {
                __nv_bfloat16* Bn = sB + (cur ^ 1) * (128 * BPITCH);
#pragma unroll
                for (int i = 0; i < 4; i++) {
                    int cid = tid + i * 256;
                    int row = cid >> 3, ch = cid & 7;
                    *(uint4*)&Bn[row * BPITCH + ch * 8] = pre[i];
                }
                __syncthreads();
            }
        }

        // epilogue: store approx sims as fp16
#pragma unroll
        for (int mt = 0; mt < 2; mt++) {
            int r0 = m0 + wm * 32 + mt * 16 + g;
#pragma unroll
            for (int nt = 0; nt < 8; nt++) {
                int col = kt + wn * 64 + nt * 8 + q * 2;
                __half2 h01 = __floats2half2_rn(acc[mt][nt][0], acc[mt][nt][1]);
                __half2 h23 = __floats2half2_rn(acc[mt][nt][2], acc[mt][nt][3]);
                *(__half2*)&g_sim[(size_t)r0 * KK + col]       = h01;
                *(__half2*)&g_sim[(size_t)(r0 + 8) * KK + col] = h23;
            }
        }
    }
}

// ---------------- kernel D: scan sims, exact-fp32 rescore candidates ----------------
__device__ __forceinline__ float exact_dot(const float* __restrict__ x, int code) {
    const float* w = g_what + (size_t)code * DD;
    float s = 0.0f;
#pragma unroll 8
    for (int d = 0; d < DD; d += 4) {
        float4 xv = *(const float4*)(x + d);
        float4 wv = *(const float4*)(w + d);
        s = fmaf(xv.x, wv.x, s);
        s = fmaf(xv.y, wv.y, s);
        s = fmaf(xv.z, wv.z, s);
        s = fmaf(xv.w, wv.w, s);
    }
    return s;
}

__global__ __launch_bounds__(256) void k_select() {
    int warp = threadIdx.x >> 5, lane = threadIdx.x & 31;
    int token = blockIdx.x * 8 + warp;
    const __half* sims = g_sim + (size_t)token * KK + lane * 128;

    uint4 v[16];
#pragma unroll
    for (int i = 0; i < 16; i++) v[i] = *(const uint4*)(sims + i * 8);

    // warp max of approx sims
    __half2 mm = *(__half2*)&v[0].x;
#pragma unroll
    for (int i = 0; i < 16; i++) {
        const unsigned* wds = (const unsigned*)&v[i];
#pragma unroll
        for (int j = 0; j < 4; j++) {
            __half2 h = *(const __half2*)&wds[j];
            mm = __hmax2(mm, h);
        }
    }
    float lmax = fmaxf(__low2float(mm), __high2float(mm));
#pragma unroll
    for (int o = 16; o; o >>= 1)
        lmax = fmaxf(lmax, __shfl_xor_sync(0xffffffffu, lmax, o));
    float thr = lmax - MARGIN;

    // exact rescore of candidates (ascending code order within lane)
    float bv = -3.4e38f;
    int   bc = 0x7fffffff;
    const float* x = g_xT + (size_t)token * DD;
#pragma unroll
    for (int i = 0; i < 16; i++) {
        const unsigned* wds = (const unsigned*)&v[i];
#pragma unroll
        for (int j = 0; j < 4; j++) {
            __half2 h = *(const __half2*)&wds[j];
            float f0 = __low2float(h), f1 = __high2float(h);
            int cb = lane * 128 + i * 8 + j * 2;
            if (f0 >= thr) {
                float e = exact_dot(x, cb);
                if (e > bv) { bv = e; bc = cb; }
            }
            if (f1 >= thr) {
                float e = exact_dot(x, cb + 1);
                if (e > bv) { bv = e; bc = cb + 1; }
            }
        }
    }
    // warp reduce with first-index tie-break
#pragma unroll
    for (int o = 16; o; o >>= 1) {
        float ov = __shfl_xor_sync(0xffffffffu, bv, o);
        int   oc = __shfl_xor_sync(0xffffffffu, bc, o);
        if (ov > bv || (ov == bv && oc < bc)) { bv = ov; bc = oc; }
    }
    if (lane == 0) {
        g_idx[token] = bc;
        atomicAdd(&g_hist[bc], 1);
    }
}

// ---------------- kernel E: gather codes -> output + loss partials ----------------
__global__ void k_gather(const float* __restrict__ in, const float* __restrict__ w,
                         float* __restrict__ out) {
    __shared__ float red[256];
    int gidx = blockIdx.x * 256 + threadIdx.x;   // 0 .. VV/4-1
    int m = gidx << 2;
    int b   = m >> 20;
    int rem = m & ((1 << 20) - 1);
    int d   = rem >> 12;
    int l   = rem & (LLEN - 1);
    int n   = (b << 12) + l;
    int4 id4 = *(const int4*)(g_idx + n);
    float4 xv = *(const float4*)(in + m);
    float4 qv;
    qv.x = w[(size_t)id4.x * DD + d];
    qv.y = w[(size_t)id4.y * DD + d];
    qv.z = w[(size_t)id4.z * DD + d];
    qv.w = w[(size_t)id4.w * DD + d];
    *(float4*)(out + m) = qv;
    float dx = qv.x - xv.x, dy = qv.y - xv.y, dz = qv.z - xv.z, dw = qv.w - xv.w;
    red[threadIdx.x] = dx*dx + dy*dy + dz*dz + dw*dw;
    __syncthreads();
#pragma unroll
    for (int o = 128; o; o >>= 1) {
        if (threadIdx.x < o) red[threadIdx.x] += red[threadIdx.x + o];
        __syncthreads();
    }
    if (threadIdx.x == 0) g_partials[blockIdx.x] = red[0];
}

__global__ void k_zero_hist() { g_hist[blockIdx.x * 256 + threadIdx.x] = 0; }

// ---------------- final scalars: loss + perplexity ----------------
__global__ void k_final(float* __restrict__ out, int out_size) {
    __shared__ float red[256];
    int t = threadIdx.x;
    float s = 0.0f;
    for (int k = t; k < 8192; k += 256) s += g_partials[k];
    red[t] = s; __syncthreads();
#pragma unroll
    for (int o = 128; o; o >>= 1) { if (t < o) red[t] += red[t + o]; __syncthreads(); }
    float loss = 1.25f * red[0] / (float)VV;
    __syncthreads();
    float p = 0.0f;
    for (int k = t; k < KK; k += 256) {
        float pv = (float)g_hist[k] * (1.0f / (float)NN);
        p += pv * logf(pv + 1e-10f);
    }
    red[t] = p; __syncthreads();
#pragma unroll
    for (int o = 128; o; o >>= 1) { if (t < o) red[t] += red[t + o]; __syncthreads(); }
    if (t == 0 && out_size >= VV + 2) {
        out[VV]     = loss;
        out[VV + 1] = expf(-red[0]);
    }
}

extern "C" void kernel_launch(void* const* d_in, const int* in_sizes, int n_in,
                              void* d_out, int out_size) {
    const float* inputs = (const float*)d_in[0];
    const float* weight = (const float*)d_in[1];
    if (n_in >= 2 && in_sizes[0] == KK * DD && in_sizes[1] == VV) {
        inputs = (const float*)d_in[1];
        weight = (const float*)d_in[0];
    }
    float* out = (float*)d_out;

    static int smem_set = 0;
    const int SIM_SMEM = (128 * APITCH + 2 * 128 * BPITCH) * (int)sizeof(__nv_bfloat16);
    if (!smem_set) {
        cudaFuncSetAttribute(k_sim, cudaFuncAttributeMaxDynamicSharedMemorySize, SIM_SMEM);
        smem_set = 1;
    }

    k_norm_w<<<512, 256>>>(weight);
    k_transpose<<<dim3(LLEN / 32, DD / 32, BB), dim3(32, 8)>>>(inputs);
    k_sim<<<NN / 128, 256, SIM_SMEM>>>();
    k_zero_hist<<<KK / 256, 256>>>();
    k_select<<<NN / 8, 256>>>();
    k_gather<<<VV / 1024, 256>>>(inputs, weight, out);
    k_final<<<1, 256>>>(out, out_size);
}